// round 1
// baseline (speedup 1.0000x reference)
#include <cuda_runtime.h>

#define NN 100000
#define EE 1600000
#define DD 64
#define CHUNK 1024
#define NBLK ((NN + CHUNK - 1) / CHUNK)   // 98

// ---- scratch (device globals; no allocation allowed) ----
__device__ int   g_count[NN];
__device__ float g_dis[NN];
__device__ int   g_rowptr[NN + 1];
__device__ int   g_cursor[NN];
__device__ int   g_bsum[NBLK];
__device__ int   g_csrsrc[EE];
__device__ float g_csrw[EE];
__device__ float g_h[NN * DD];
__device__ float g_o[NN * DD];

// ---------------- CSR build ----------------

__global__ void k_zero() {
    int i = blockIdx.x * blockDim.x + threadIdx.x;
    if (i < NN) g_count[i] = 0;
}

__global__ void k_count(const int* __restrict__ ei) {
    const int* dst = ei + EE;
    int e = blockIdx.x * blockDim.x + threadIdx.x;
    if (e < EE) atomicAdd(&g_count[dst[e]], 1);
}

// per-chunk exclusive scan into rowptr (local), chunk totals into g_bsum
__global__ void k_scan1() {
    __shared__ int s[CHUNK];
    int t = threadIdx.x;
    int i = blockIdx.x * CHUNK + t;
    int v = (i < NN) ? g_count[i] : 0;
    s[t] = v;
    __syncthreads();
    // Hillis-Steele inclusive scan
    for (int off = 1; off < CHUNK; off <<= 1) {
        int add = (t >= off) ? s[t - off] : 0;
        __syncthreads();
        s[t] += add;
        __syncthreads();
    }
    if (i < NN) g_rowptr[i] = s[t] - v;  // exclusive
    if (t == CHUNK - 1) g_bsum[blockIdx.x] = s[t];
}

__global__ void k_scan2() {
    __shared__ int s[NBLK];
    int t = threadIdx.x;
    if (t < NBLK) s[t] = g_bsum[t];
    __syncthreads();
    if (t == 0) {
        int acc = 0;
        for (int b = 0; b < NBLK; b++) { int v = s[b]; s[b] = acc; acc += v; }
        g_rowptr[NN] = EE;
    }
    __syncthreads();
    if (t < NBLK) g_bsum[t] = s[t];
}

__global__ void k_scan3() {
    int i = blockIdx.x * CHUNK + threadIdx.x;
    if (i < NN) {
        int rp = g_rowptr[i] + g_bsum[blockIdx.x];
        g_rowptr[i] = rp;
        g_cursor[i] = rp;
        g_dis[i] = rsqrtf((float)(g_count[i] + 1));  // +1 self-loop; deg>0 always
    }
}

__global__ void k_fill(const int* __restrict__ ei) {
    const int* src = ei;
    const int* dst = ei + EE;
    int e = blockIdx.x * blockDim.x + threadIdx.x;
    if (e < EE) {
        int s = src[e], d = dst[e];
        int pos = atomicAdd(&g_cursor[d], 1);
        g_csrsrc[pos] = s;
        g_csrw[pos]   = g_dis[s] * g_dis[d];
    }
}

// ---------------- dense GEMM: h = x @ W (64x64 W in smem) ----------------

__global__ void k_gemm(const float* __restrict__ x, const float* __restrict__ W,
                       float* __restrict__ h) {
    __shared__ float sW[64 * 64];
    int t = threadIdx.x;
    for (int i = t; i < 64 * 64; i += blockDim.x) sW[i] = W[i];
    __syncthreads();
    int lane  = t & 31;
    int wid   = t >> 5;
    int warps = (gridDim.x * blockDim.x) >> 5;
    for (int r = blockIdx.x * (blockDim.x >> 5) + wid; r < NN; r += warps) {
        float x0 = x[r * 64 + lane];
        float x1 = x[r * 64 + 32 + lane];
        float a0 = 0.f, a1 = 0.f;
#pragma unroll
        for (int k = 0; k < 32; k++) {
            float xv = __shfl_sync(0xffffffffu, x0, k);
            a0 += xv * sW[k * 64 + lane];
            a1 += xv * sW[k * 64 + 32 + lane];
        }
#pragma unroll
        for (int k = 0; k < 32; k++) {
            float xv = __shfl_sync(0xffffffffu, x1, k);
            a0 += xv * sW[(k + 32) * 64 + lane];
            a1 += xv * sW[(k + 32) * 64 + 32 + lane];
        }
        h[r * 64 + lane]      = a0;
        h[r * 64 + 32 + lane] = a1;
    }
}

// ---------------- aggregation: out[v] = sum_{e: dst=v} w_e * h[src_e] + dis[v]^2*h[v] + b
// one warp per node; each lane owns 2 channels (float2)

template <bool RELU>
__global__ void k_agg(const float* __restrict__ h, const float* __restrict__ b,
                      float* __restrict__ out) {
    int lane = threadIdx.x & 31;
    int wid  = threadIdx.x >> 5;
    int v    = blockIdx.x * 8 + wid;
    if (v >= NN) return;

    float2 bb = *(const float2*)(b + lane * 2);
    float  dv = g_dis[v];
    float2 hv = *(const float2*)(h + v * 64 + lane * 2);
    float  self = dv * dv;
    float  ax = bb.x + self * hv.x;
    float  ay = bb.y + self * hv.y;

    int beg = g_rowptr[v];
    int end = g_rowptr[v + 1];
    for (int j = beg; j < end; j += 32) {
        int idx = j + lane;
        int s = 0; float w = 0.f;
        if (idx < end) { s = g_csrsrc[idx]; w = g_csrw[idx]; }
        int cnt = min(32, end - j);
        int k = 0;
        // manual 4x unroll: 4 independent gathers in flight
        for (; k + 4 <= cnt; k += 4) {
            int   s0 = __shfl_sync(0xffffffffu, s, k);
            int   s1 = __shfl_sync(0xffffffffu, s, k + 1);
            int   s2 = __shfl_sync(0xffffffffu, s, k + 2);
            int   s3 = __shfl_sync(0xffffffffu, s, k + 3);
            float w0 = __shfl_sync(0xffffffffu, w, k);
            float w1 = __shfl_sync(0xffffffffu, w, k + 1);
            float w2 = __shfl_sync(0xffffffffu, w, k + 2);
            float w3 = __shfl_sync(0xffffffffu, w, k + 3);
            float2 h0 = *(const float2*)(h + s0 * 64 + lane * 2);
            float2 h1 = *(const float2*)(h + s1 * 64 + lane * 2);
            float2 h2 = *(const float2*)(h + s2 * 64 + lane * 2);
            float2 h3 = *(const float2*)(h + s3 * 64 + lane * 2);
            ax += w0 * h0.x; ay += w0 * h0.y;
            ax += w1 * h1.x; ay += w1 * h1.y;
            ax += w2 * h2.x; ay += w2 * h2.y;
            ax += w3 * h3.x; ay += w3 * h3.y;
        }
        for (; k < cnt; k++) {
            int   sk = __shfl_sync(0xffffffffu, s, k);
            float wk = __shfl_sync(0xffffffffu, w, k);
            float2 hs = *(const float2*)(h + sk * 64 + lane * 2);
            ax += wk * hs.x; ay += wk * hs.y;
        }
    }
    if (RELU) { ax = fmaxf(ax, 0.f); ay = fmaxf(ay, 0.f); }
    float2 r; r.x = ax; r.y = ay;
    *(float2*)(out + v * 64 + lane * 2) = r;
}

// ---------------- launch ----------------

extern "C" void kernel_launch(void* const* d_in, const int* in_sizes, int n_in,
                              void* d_out, int out_size) {
    const float* x  = (const float*)d_in[0];
    const int*   ei = (const int*)d_in[1];
    const float* W1 = (const float*)d_in[2];
    const float* b1 = (const float*)d_in[3];
    const float* W2 = (const float*)d_in[4];
    const float* b2 = (const float*)d_in[5];
    const float* W3 = (const float*)d_in[6];
    const float* b3 = (const float*)d_in[7];
    float* out = (float*)d_out;

    float *h, *o;
    cudaGetSymbolAddress((void**)&h, g_h);
    cudaGetSymbolAddress((void**)&o, g_o);

    const int T = 256;
    // CSR build
    k_zero<<<(NN + T - 1) / T, T>>>();
    k_count<<<(EE + T - 1) / T, T>>>(ei);
    k_scan1<<<NBLK, CHUNK>>>();
    k_scan2<<<1, 128>>>();
    k_scan3<<<NBLK, CHUNK>>>();
    k_fill<<<(EE + T - 1) / T, T>>>(ei);

    const int GEMM_GRID = 1184;         // grid-stride; W loaded once per block
    const int AGG_GRID  = (NN + 7) / 8; // one warp per node, 8 warps/block

    // layer 1
    k_gemm<<<GEMM_GRID, T>>>(x, W1, h);
    k_agg<true><<<AGG_GRID, T>>>(h, b1, o);
    // layer 2
    k_gemm<<<GEMM_GRID, T>>>(o, W2, h);
    k_agg<true><<<AGG_GRID, T>>>(h, b2, o);
    // layer 3
    k_gemm<<<GEMM_GRID, T>>>(o, W3, h);
    k_agg<false><<<AGG_GRID, T>>>(h, b3, out);
}

// round 2
// speedup vs baseline: 1.5978x; 1.5978x over previous
#include <cuda_runtime.h>

#define NN 100000
#define EE 1600000
#define DD 64
#define CHUNK 1024
#define NBLK ((NN + CHUNK - 1) / CHUNK)   // 98

// ---- scratch (device globals; no allocation allowed) ----
__device__ int   g_count[NN];
__device__ float g_dis[NN];
__device__ int   g_rowptr[NN + 1];
__device__ int   g_cursor[NN];
__device__ int   g_bsum[NBLK];
__device__ int   g_csrsrc[EE];
__device__ float g_csrw[EE];
__device__ float g_h[NN * DD];
__device__ float g_o[NN * DD];

// ---------------- CSR build ----------------

__global__ void k_count(const int* __restrict__ ei) {
    const int* dst = ei + EE;
    int e = blockIdx.x * blockDim.x + threadIdx.x;
    if (e < EE) atomicAdd(&g_count[dst[e]], 1);
}

// per-chunk exclusive scan into rowptr (local), chunk totals into g_bsum
__global__ void k_scan1() {
    __shared__ int s[CHUNK];
    int t = threadIdx.x;
    int i = blockIdx.x * CHUNK + t;
    int v = (i < NN) ? g_count[i] : 0;
    s[t] = v;
    __syncthreads();
    for (int off = 1; off < CHUNK; off <<= 1) {
        int add = (t >= off) ? s[t - off] : 0;
        __syncthreads();
        s[t] += add;
        __syncthreads();
    }
    if (i < NN) g_rowptr[i] = s[t] - v;  // exclusive
    if (t == CHUNK - 1) g_bsum[blockIdx.x] = s[t];
}

// parallel exclusive scan of the 98 block sums
__global__ void k_scan2() {
    __shared__ int s[128];
    int t = threadIdx.x;
    int v = (t < NBLK) ? g_bsum[t] : 0;
    s[t] = v;
    __syncthreads();
    for (int off = 1; off < 128; off <<= 1) {
        int add = (t >= off) ? s[t - off] : 0;
        __syncthreads();
        s[t] += add;
        __syncthreads();
    }
    if (t < NBLK) g_bsum[t] = s[t] - v;  // exclusive
    if (t == 0) g_rowptr[NN] = EE;
}

__global__ void k_scan3() {
    int i = blockIdx.x * CHUNK + threadIdx.x;
    if (i < NN) {
        int rp = g_rowptr[i] + g_bsum[blockIdx.x];
        g_rowptr[i] = rp;
        g_cursor[i] = rp;
        g_dis[i] = rsqrtf((float)(g_count[i] + 1));  // +1 self-loop
    }
}

__global__ void k_fill(const int* __restrict__ ei) {
    const int* src = ei;
    const int* dst = ei + EE;
    int e = blockIdx.x * blockDim.x + threadIdx.x;
    if (e < EE) {
        int s = src[e], d = dst[e];
        int pos = atomicAdd(&g_cursor[d], 1);
        g_csrsrc[pos] = s;
        g_csrw[pos]   = g_dis[s] * g_dis[d];
    }
}

// ---------------- fused layer: out = relu( (A_norm @ xin) @ W + b ) -------
// Uses (A x) W == A (x W). One warp aggregates 4 nodes (gather over raw
// features), stashes 4x64 aggregate to smem, then does the 64x64 GEMM
// epilogue with W in smem (amortized over 4 nodes).

template <bool RELU>
__global__ void __launch_bounds__(256) k_layer(
        const float* __restrict__ xin, const float* __restrict__ W,
        const float* __restrict__ b, float* __restrict__ out) {
    __shared__ float sW[64 * 64];          // 16 KB
    __shared__ float sA[8][4 * 64];        // 8 KB, per-warp aggregate stash
    int t = threadIdx.x;
    for (int i = t * 4; i < 64 * 64; i += 256 * 4)
        *(float4*)&sW[i] = *(const float4*)&W[i];
    __syncthreads();

    int lane = t & 31;
    int wid  = t >> 5;
    int vbase = (blockIdx.x * 8 + wid) * 4;   // 100000 = 3125*8*4 exactly

    float2 acc[4];
#pragma unroll
    for (int n = 0; n < 4; n++) {
        int v = vbase + n;
        float  dv   = g_dis[v];
        float2 hv   = *(const float2*)(xin + (size_t)v * 64 + lane * 2);
        float  self = dv * dv;
        float  ax = self * hv.x;
        float  ay = self * hv.y;
        int beg = g_rowptr[v];
        int end = g_rowptr[v + 1];
        for (int j = beg; j < end; j += 32) {
            int idx = j + lane;
            int s = 0; float w = 0.f;
            if (idx < end) { s = g_csrsrc[idx]; w = g_csrw[idx]; }
            int cnt = min(32, end - j);
            int k = 0;
            // 8 independent gathers in flight
            for (; k + 8 <= cnt; k += 8) {
                int   s0 = __shfl_sync(0xffffffffu, s, k);
                int   s1 = __shfl_sync(0xffffffffu, s, k + 1);
                int   s2 = __shfl_sync(0xffffffffu, s, k + 2);
                int   s3 = __shfl_sync(0xffffffffu, s, k + 3);
                int   s4 = __shfl_sync(0xffffffffu, s, k + 4);
                int   s5 = __shfl_sync(0xffffffffu, s, k + 5);
                int   s6 = __shfl_sync(0xffffffffu, s, k + 6);
                int   s7 = __shfl_sync(0xffffffffu, s, k + 7);
                float w0 = __shfl_sync(0xffffffffu, w, k);
                float w1 = __shfl_sync(0xffffffffu, w, k + 1);
                float w2 = __shfl_sync(0xffffffffu, w, k + 2);
                float w3 = __shfl_sync(0xffffffffu, w, k + 3);
                float w4 = __shfl_sync(0xffffffffu, w, k + 4);
                float w5 = __shfl_sync(0xffffffffu, w, k + 5);
                float w6 = __shfl_sync(0xffffffffu, w, k + 6);
                float w7 = __shfl_sync(0xffffffffu, w, k + 7);
                float2 h0 = *(const float2*)(xin + (size_t)s0 * 64 + lane * 2);
                float2 h1 = *(const float2*)(xin + (size_t)s1 * 64 + lane * 2);
                float2 h2 = *(const float2*)(xin + (size_t)s2 * 64 + lane * 2);
                float2 h3 = *(const float2*)(xin + (size_t)s3 * 64 + lane * 2);
                float2 h4 = *(const float2*)(xin + (size_t)s4 * 64 + lane * 2);
                float2 h5 = *(const float2*)(xin + (size_t)s5 * 64 + lane * 2);
                float2 h6 = *(const float2*)(xin + (size_t)s6 * 64 + lane * 2);
                float2 h7 = *(const float2*)(xin + (size_t)s7 * 64 + lane * 2);
                ax += w0 * h0.x; ay += w0 * h0.y;
                ax += w1 * h1.x; ay += w1 * h1.y;
                ax += w2 * h2.x; ay += w2 * h2.y;
                ax += w3 * h3.x; ay += w3 * h3.y;
                ax += w4 * h4.x; ay += w4 * h4.y;
                ax += w5 * h5.x; ay += w5 * h5.y;
                ax += w6 * h6.x; ay += w6 * h6.y;
                ax += w7 * h7.x; ay += w7 * h7.y;
            }
            for (; k < cnt; k++) {
                int   sk = __shfl_sync(0xffffffffu, s, k);
                float wk = __shfl_sync(0xffffffffu, w, k);
                float2 hs = *(const float2*)(xin + (size_t)sk * 64 + lane * 2);
                ax += wk * hs.x; ay += wk * hs.y;
            }
        }
        acc[n].x = ax; acc[n].y = ay;
    }

    // stash aggregates, then GEMM epilogue: y[n] = acc[n] @ W + b
#pragma unroll
    for (int n = 0; n < 4; n++)
        *(float2*)&sA[wid][n * 64 + lane * 2] = acc[n];
    __syncwarp();

    float2 bb = *(const float2*)(b + lane * 2);
    float2 y0 = bb, y1 = bb, y2 = bb, y3 = bb;
#pragma unroll 8
    for (int k = 0; k < 64; k++) {
        float2 wk = *(const float2*)&sW[k * 64 + lane * 2];
        float a0 = sA[wid][0 * 64 + k];
        float a1 = sA[wid][1 * 64 + k];
        float a2 = sA[wid][2 * 64 + k];
        float a3 = sA[wid][3 * 64 + k];
        y0.x += a0 * wk.x; y0.y += a0 * wk.y;
        y1.x += a1 * wk.x; y1.y += a1 * wk.y;
        y2.x += a2 * wk.x; y2.y += a2 * wk.y;
        y3.x += a3 * wk.x; y3.y += a3 * wk.y;
    }
    if (RELU) {
        y0.x = fmaxf(y0.x, 0.f); y0.y = fmaxf(y0.y, 0.f);
        y1.x = fmaxf(y1.x, 0.f); y1.y = fmaxf(y1.y, 0.f);
        y2.x = fmaxf(y2.x, 0.f); y2.y = fmaxf(y2.y, 0.f);
        y3.x = fmaxf(y3.x, 0.f); y3.y = fmaxf(y3.y, 0.f);
    }
    *(float2*)(out + (size_t)(vbase + 0) * 64 + lane * 2) = y0;
    *(float2*)(out + (size_t)(vbase + 1) * 64 + lane * 2) = y1;
    *(float2*)(out + (size_t)(vbase + 2) * 64 + lane * 2) = y2;
    *(float2*)(out + (size_t)(vbase + 3) * 64 + lane * 2) = y3;
}

// ---------------- launch ----------------

extern "C" void kernel_launch(void* const* d_in, const int* in_sizes, int n_in,
                              void* d_out, int out_size) {
    const float* x  = (const float*)d_in[0];
    const int*   ei = (const int*)d_in[1];
    const float* W1 = (const float*)d_in[2];
    const float* b1 = (const float*)d_in[3];
    const float* W2 = (const float*)d_in[4];
    const float* b2 = (const float*)d_in[5];
    const float* W3 = (const float*)d_in[6];
    const float* b3 = (const float*)d_in[7];
    float* out = (float*)d_out;

    float *h, *o;
    int *cnt;
    cudaGetSymbolAddress((void**)&h, g_h);
    cudaGetSymbolAddress((void**)&o, g_o);
    cudaGetSymbolAddress((void**)&cnt, g_count);

    const int T = 256;
    // CSR build
    cudaMemsetAsync(cnt, 0, NN * sizeof(int));
    k_count<<<(EE + T - 1) / T, T>>>(ei);
    k_scan1<<<NBLK, CHUNK>>>();
    k_scan2<<<1, 128>>>();
    k_scan3<<<NBLK, CHUNK>>>();
    k_fill<<<(EE + T - 1) / T, T>>>(ei);

    const int LAYER_GRID = NN / 32;   // 3125: 8 warps/block * 4 nodes/warp

    k_layer<true ><<<LAYER_GRID, T>>>(x, W1, b1, h);
    k_layer<true ><<<LAYER_GRID, T>>>(h, W2, b2, o);
    k_layer<false><<<LAYER_GRID, T>>>(o, W3, b3, out);
}

// round 3
// speedup vs baseline: 1.6631x; 1.0409x over previous
#include <cuda_runtime.h>
#include <cuda_fp16.h>

#define NN 100000
#define EE 1600000
#define DD 64
#define CHUNK 1024
#define NBLK ((NN + CHUNK - 1) / CHUNK)   // 98

// ---- scratch (device globals; no allocation allowed) ----
__device__ int    g_count[NN];
__device__ float  g_dis[NN];
__device__ int    g_rowptr[NN + 1];
__device__ int    g_cursor[NN];
__device__ int    g_bsum[NBLK];
__device__ int2   g_csre[EE];          // {src, w-as-int}
__device__ __half g_hA[NN * DD];
__device__ __half g_hB[NN * DD];

// ---------------- CSR build ----------------

__global__ void k_count(const int* __restrict__ ei) {
    const int* dst = ei + EE;
    int e = blockIdx.x * blockDim.x + threadIdx.x;
    if (e < EE) atomicAdd(&g_count[dst[e]], 1);
}

// per-chunk exclusive scan into rowptr (local), chunk totals into g_bsum;
// also computes deg_inv_sqrt (depends only on count).
__global__ void k_scan1() {
    __shared__ int s[CHUNK];
    int t = threadIdx.x;
    int i = blockIdx.x * CHUNK + t;
    int v = (i < NN) ? g_count[i] : 0;
    s[t] = v;
    __syncthreads();
    for (int off = 1; off < CHUNK; off <<= 1) {
        int add = (t >= off) ? s[t - off] : 0;
        __syncthreads();
        s[t] += add;
        __syncthreads();
    }
    if (i < NN) {
        g_rowptr[i] = s[t] - v;  // exclusive (local)
        g_dis[i] = rsqrtf((float)(v + 1));  // +1 self-loop
    }
    if (t == CHUNK - 1) g_bsum[blockIdx.x] = s[t];
}

// parallel exclusive scan of the 98 block sums
__global__ void k_scan2() {
    __shared__ int s[128];
    int t = threadIdx.x;
    int v = (t < NBLK) ? g_bsum[t] : 0;
    s[t] = v;
    __syncthreads();
    for (int off = 1; off < 128; off <<= 1) {
        int add = (t >= off) ? s[t - off] : 0;
        __syncthreads();
        s[t] += add;
        __syncthreads();
    }
    if (t < NBLK) g_bsum[t] = s[t] - v;  // exclusive
    if (t == 0) g_rowptr[NN] = EE;
}

__global__ void k_scan3() {
    int i = blockIdx.x * CHUNK + threadIdx.x;
    if (i < NN) {
        int rp = g_rowptr[i] + g_bsum[blockIdx.x];
        g_rowptr[i] = rp;
        g_cursor[i] = rp;
    }
}

__global__ void k_fill(const int* __restrict__ ei) {
    const int* src = ei;
    const int* dst = ei + EE;
    int e = blockIdx.x * blockDim.x + threadIdx.x;
    if (e < EE) {
        int s = src[e], d = dst[e];
        int pos = atomicAdd(&g_cursor[d], 1);
        int2 p;
        p.x = s;
        p.y = __float_as_int(g_dis[s] * g_dis[d]);
        g_csre[pos] = p;
    }
}

// ---------------- convert x (fp32) -> fp16 working buffer ----------------

__global__ void k_cvt(const float* __restrict__ x) {
    int i = blockIdx.x * blockDim.x + threadIdx.x;
    if (i < NN * DD / 2) {
        float2 v = ((const float2*)x)[i];
        ((__half2*)g_hA)[i] = __float22half2_rn(v);
    }
}

// ---------------- fused layer: out = relu( (A_norm @ xin) @ W + b ) -------
// Gathers read fp16 rows (128B/edge), accumulate fp32, GEMM epilogue fp32.
// One warp handles 4 nodes; lane owns 2 channels.

template <bool RELU, bool OUT16>
__global__ void __launch_bounds__(256) k_layer(
        const __half* __restrict__ xin, const float* __restrict__ W,
        const float* __restrict__ b, __half* __restrict__ out16,
        float* __restrict__ out32) {
    __shared__ float sW[64 * 64];          // 16 KB
    __shared__ float sA[8][4 * 64];        // 8 KB, per-warp aggregate stash
    int t = threadIdx.x;
    for (int i = t * 4; i < 64 * 64; i += 256 * 4)
        *(float4*)&sW[i] = *(const float4*)&W[i];
    __syncthreads();

    int lane = t & 31;
    int wid  = t >> 5;
    int vbase = (blockIdx.x * 8 + wid) * 4;   // 100000 = 3125*8*4 exactly

    const __half2* __restrict__ xin2 = (const __half2*)xin;

    float2 acc[4];
#pragma unroll
    for (int n = 0; n < 4; n++) {
        int v = vbase + n;
        float  dv   = g_dis[v];
        float2 hv   = __half22float2(xin2[(size_t)v * 32 + lane]);
        float  self = dv * dv;
        float  ax = self * hv.x;
        float  ay = self * hv.y;
        int beg = g_rowptr[v];
        int end = g_rowptr[v + 1];
        for (int j = beg; j < end; j += 32) {
            int idx = j + lane;
            int sl = 0; float wl = 0.f;
            if (idx < end) {
                int2 e = g_csre[idx];
                sl = e.x; wl = __int_as_float(e.y);
            }
            int cnt = min(32, end - j);
            int k = 0;
            // 8 independent 4B gathers in flight
            for (; k + 8 <= cnt; k += 8) {
                int   s0 = __shfl_sync(0xffffffffu, sl, k);
                int   s1 = __shfl_sync(0xffffffffu, sl, k + 1);
                int   s2 = __shfl_sync(0xffffffffu, sl, k + 2);
                int   s3 = __shfl_sync(0xffffffffu, sl, k + 3);
                int   s4 = __shfl_sync(0xffffffffu, sl, k + 4);
                int   s5 = __shfl_sync(0xffffffffu, sl, k + 5);
                int   s6 = __shfl_sync(0xffffffffu, sl, k + 6);
                int   s7 = __shfl_sync(0xffffffffu, sl, k + 7);
                float w0 = __shfl_sync(0xffffffffu, wl, k);
                float w1 = __shfl_sync(0xffffffffu, wl, k + 1);
                float w2 = __shfl_sync(0xffffffffu, wl, k + 2);
                float w3 = __shfl_sync(0xffffffffu, wl, k + 3);
                float w4 = __shfl_sync(0xffffffffu, wl, k + 4);
                float w5 = __shfl_sync(0xffffffffu, wl, k + 5);
                float w6 = __shfl_sync(0xffffffffu, wl, k + 6);
                float w7 = __shfl_sync(0xffffffffu, wl, k + 7);
                __half2 h0 = xin2[(size_t)s0 * 32 + lane];
                __half2 h1 = xin2[(size_t)s1 * 32 + lane];
                __half2 h2 = xin2[(size_t)s2 * 32 + lane];
                __half2 h3 = xin2[(size_t)s3 * 32 + lane];
                __half2 h4 = xin2[(size_t)s4 * 32 + lane];
                __half2 h5 = xin2[(size_t)s5 * 32 + lane];
                __half2 h6 = xin2[(size_t)s6 * 32 + lane];
                __half2 h7 = xin2[(size_t)s7 * 32 + lane];
                float2 f0 = __half22float2(h0);
                float2 f1 = __half22float2(h1);
                float2 f2 = __half22float2(h2);
                float2 f3 = __half22float2(h3);
                float2 f4 = __half22float2(h4);
                float2 f5 = __half22float2(h5);
                float2 f6 = __half22float2(h6);
                float2 f7 = __half22float2(h7);
                ax += w0 * f0.x; ay += w0 * f0.y;
                ax += w1 * f1.x; ay += w1 * f1.y;
                ax += w2 * f2.x; ay += w2 * f2.y;
                ax += w3 * f3.x; ay += w3 * f3.y;
                ax += w4 * f4.x; ay += w4 * f4.y;
                ax += w5 * f5.x; ay += w5 * f5.y;
                ax += w6 * f6.x; ay += w6 * f6.y;
                ax += w7 * f7.x; ay += w7 * f7.y;
            }
            for (; k < cnt; k++) {
                int   sk = __shfl_sync(0xffffffffu, sl, k);
                float wk = __shfl_sync(0xffffffffu, wl, k);
                float2 hs = __half22float2(xin2[(size_t)sk * 32 + lane]);
                ax += wk * hs.x; ay += wk * hs.y;
            }
        }
        acc[n].x = ax; acc[n].y = ay;
    }

    // stash aggregates, then GEMM epilogue: y[n] = acc[n] @ W + b
#pragma unroll
    for (int n = 0; n < 4; n++)
        *(float2*)&sA[wid][n * 64 + lane * 2] = acc[n];
    __syncwarp();

    float2 bb = *(const float2*)(b + lane * 2);
    float2 y0 = bb, y1 = bb, y2 = bb, y3 = bb;
#pragma unroll 8
    for (int k = 0; k < 64; k++) {
        float2 wk = *(const float2*)&sW[k * 64 + lane * 2];
        float a0 = sA[wid][0 * 64 + k];
        float a1 = sA[wid][1 * 64 + k];
        float a2 = sA[wid][2 * 64 + k];
        float a3 = sA[wid][3 * 64 + k];
        y0.x += a0 * wk.x; y0.y += a0 * wk.y;
        y1.x += a1 * wk.x; y1.y += a1 * wk.y;
        y2.x += a2 * wk.x; y2.y += a2 * wk.y;
        y3.x += a3 * wk.x; y3.y += a3 * wk.y;
    }
    if (RELU) {
        y0.x = fmaxf(y0.x, 0.f); y0.y = fmaxf(y0.y, 0.f);
        y1.x = fmaxf(y1.x, 0.f); y1.y = fmaxf(y1.y, 0.f);
        y2.x = fmaxf(y2.x, 0.f); y2.y = fmaxf(y2.y, 0.f);
        y3.x = fmaxf(y3.x, 0.f); y3.y = fmaxf(y3.y, 0.f);
    }
    if (OUT16) {
        __half2* o2 = (__half2*)out16;
        o2[(size_t)(vbase + 0) * 32 + lane] = __float22half2_rn(y0);
        o2[(size_t)(vbase + 1) * 32 + lane] = __float22half2_rn(y1);
        o2[(size_t)(vbase + 2) * 32 + lane] = __float22half2_rn(y2);
        o2[(size_t)(vbase + 3) * 32 + lane] = __float22half2_rn(y3);
    } else {
        *(float2*)(out32 + (size_t)(vbase + 0) * 64 + lane * 2) = y0;
        *(float2*)(out32 + (size_t)(vbase + 1) * 64 + lane * 2) = y1;
        *(float2*)(out32 + (size_t)(vbase + 2) * 64 + lane * 2) = y2;
        *(float2*)(out32 + (size_t)(vbase + 3) * 64 + lane * 2) = y3;
    }
}

// ---------------- launch ----------------

extern "C" void kernel_launch(void* const* d_in, const int* in_sizes, int n_in,
                              void* d_out, int out_size) {
    const float* x  = (const float*)d_in[0];
    const int*   ei = (const int*)d_in[1];
    const float* W1 = (const float*)d_in[2];
    const float* b1 = (const float*)d_in[3];
    const float* W2 = (const float*)d_in[4];
    const float* b2 = (const float*)d_in[5];
    const float* W3 = (const float*)d_in[6];
    const float* b3 = (const float*)d_in[7];
    float* out = (float*)d_out;

    __half *hA, *hB;
    int *cnt;
    cudaGetSymbolAddress((void**)&hA, g_hA);
    cudaGetSymbolAddress((void**)&hB, g_hB);
    cudaGetSymbolAddress((void**)&cnt, g_count);

    const int T = 256;
    // CSR build
    cudaMemsetAsync(cnt, 0, NN * sizeof(int));
    k_count<<<(EE + T - 1) / T, T>>>(ei);
    k_scan1<<<NBLK, CHUNK>>>();
    k_scan2<<<1, 128>>>();
    k_scan3<<<NBLK, CHUNK>>>();
    k_fill<<<(EE + T - 1) / T, T>>>(ei);

    // x -> fp16
    k_cvt<<<(NN * DD / 2 + T - 1) / T, T>>>(x);

    const int LAYER_GRID = NN / 32;   // 3125: 8 warps/block * 4 nodes/warp

    k_layer<true,  true ><<<LAYER_GRID, T>>>(hA, W1, b1, hB, nullptr);
    k_layer<true,  true ><<<LAYER_GRID, T>>>(hB, W2, b2, hA, nullptr);
    k_layer<false, false><<<LAYER_GRID, T>>>(hA, W3, b3, nullptr, out);
}